// round 17
// baseline (speedup 1.0000x reference)
#include <cuda_runtime.h>
#include <math.h>
#include <float.h>

#define BATCH   256
#define NLEV    4
#define CDIM    8000
#define NTOTAL  10500
#define THREADS 1024

// Packed accumulator: bits [0,48) fixed-point sum (x 2^32, all p >= 0),
// bits [48,..) arrival count. Integer adds commute exactly -> deterministic.
__device__ unsigned long long g_acc = 0ULL;

__device__ __forceinline__ void amax_comb(float& av, int& ai, float av2, int ai2) {
    if (av2 > av || (av2 == av && ai2 < ai)) { av = av2; ai = ai2; }
}

// Exp-sum + argmax over one level's prefix (N4 float4s); ITERS loads issued
// up-front for maximum memory-level parallelism.
template<int N4, int STRIDE, int ITERS, bool NEED_SUM>
__device__ __forceinline__ void accum(const float4* __restrict__ row4, int lt,
                                      float& s, float& av, int& ai) {
    float4 v[ITERS]; int id[ITERS]; bool p[ITERS];
    #pragma unroll
    for (int k = 0; k < ITERS; k++) {
        int idx = lt + k * STRIDE;
        p[k]  = idx < N4;
        id[k] = p[k] ? idx : (N4 - 1);
        v[k]  = __ldg(&row4[id[k]]);
    }
    float s0 = 0.f, s1 = 0.f, s2 = 0.f, s3 = 0.f;
    float a0 = -FLT_MAX, a1 = -FLT_MAX, a2 = -FLT_MAX, a3 = -FLT_MAX;
    int   i0 = 0x7fffffff, i1 = 0x7fffffff, i2 = 0x7fffffff, i3 = 0x7fffffff;
    #pragma unroll
    for (int k = 0; k < ITERS; k++) {
        float4 w = v[k];
        if (!p[k]) { w.x = w.y = w.z = w.w = -FLT_MAX; }   // exp->0, never argmax
        int e = 4 * id[k];
        if (NEED_SUM) {
            s0 += __expf(w.x); s1 += __expf(w.y);
            s2 += __expf(w.z); s3 += __expf(w.w);
        }
        if (w.x > a0) { a0 = w.x; i0 = e + 0; }
        if (w.y > a1) { a1 = w.y; i1 = e + 1; }
        if (w.z > a2) { a2 = w.z; i2 = e + 2; }
        if (w.w > a3) { a3 = w.w; i3 = e + 3; }
    }
    s = (s0 + s1) + (s2 + s3);
    av = a0; ai = i0;
    amax_comb(av, ai, a1, i1);
    amax_comb(av, ai, a2, i2);
    amax_comb(av, ai, a3, i3);
}

__global__ void __launch_bounds__(THREADS, 2) fused_taxanet_kernel(
    const float* __restrict__ y_pred,
    const int*   __restrict__ y_true,
    const float* __restrict__ H,
    float*       __restrict__ out)
{
    const int b    = blockIdx.x;
    const int tid  = threadIdx.x;
    const int warp = tid >> 5;
    const int lane = tid & 31;

    __shared__ float s_s[32], s_av[32];
    __shared__ int   s_ai[32];
    __shared__ float s_tlogit[4];

    const float* base = y_pred + (size_t)b * NLEV * CDIM;

    if (warp == 31) {
        // Prefetch target logits (two dependent trips, hidden by the sweep).
        if (lane < 3) {
            const int jj  = lane + 1;
            const int szs = (jj == 1) ? 400 : (jj == 2) ? 2000 : 8000;
            int tgt = __ldg(&y_true[b * NLEV + jj]);
            tgt = min(max(tgt, 0), szs - 1);
            s_tlogit[jj] = __ldg(base + (size_t)jj * CDIM + tgt);
        }
        if (lane == 0) { s_s[31] = 0.f; s_av[31] = -FLT_MAX; s_ai[31] = 0x7fffffff; }
    } else {
        // Segments: warps [0,22)->L3, [22,28)->L2, [28,30)->L1, [30]->L0
        int j, seg_base;
        if (warp < 22)      { j = 3; seg_base = 0;  }
        else if (warp < 28) { j = 2; seg_base = 22; }
        else if (warp < 30) { j = 1; seg_base = 28; }
        else                { j = 0; seg_base = 30; }
        const int lt = tid - seg_base * 32;

        const float4* row4 = reinterpret_cast<const float4*>(base + (size_t)j * CDIM);

        float s, av; int ai;
        if (j == 3)      accum<2000, 704, 3, true >(row4, lt, s, av, ai);
        else if (j == 2) accum< 500, 192, 3, true >(row4, lt, s, av, ai);
        else if (j == 1) accum< 100,  64, 2, true >(row4, lt, s, av, ai);
        else             accum<  25,  32, 1, false>(row4, lt, s, av, ai);

        #pragma unroll
        for (int o = 16; o > 0; o >>= 1) {
            float s2  = __shfl_down_sync(0xffffffffu, s,  o);
            float av2 = __shfl_down_sync(0xffffffffu, av, o);
            int   ai2 = __shfl_down_sync(0xffffffffu, ai, o);
            s += s2;
            amax_comb(av, ai, av2, ai2);
        }
        if (lane == 0) { s_s[warp] = s; s_av[warp] = av; s_ai[warp] = ai; }
    }
    __syncthreads();   // the ONLY block-wide barrier

    // Warp 0 finishes the whole block: segmented fold of 32 partials,
    // H gathers, one packed atomic.
    if (warp == 0) {
        float rs = s_s[lane], rav = s_av[lane];
        int   rai = s_ai[lane];
        // Segments in the 32 slots: L3 [0,22), L2 [22,28), L1 [28,30), L0 [30], pad [31]
        const int segsz   = (lane < 22) ? 22 : (lane < 28) ? 6 : (lane < 30) ? 2 : 1;
        const int segbase = (lane < 22) ? 0  : (lane < 28) ? 22 : (lane < 30) ? 28 : lane;
        const int w = lane - segbase;
        #pragma unroll
        for (int o = 16; o > 0; o >>= 1) {
            float s2  = __shfl_down_sync(0xffffffffu, rs,  o);
            float av2 = __shfl_down_sync(0xffffffffu, rav, o);
            int   ai2 = __shfl_down_sync(0xffffffffu, rai, o);
            if (w + o < segsz) {
                rs += s2;
                amax_comb(rav, rai, av2, ai2);
            }
        }
        // Heads: lane0->L3, lane22->L2, lane28->L1, lane30->L0.
        float nllv = 0.f;
        if (lane == 0)       nllv = __logf(rs) - s_tlogit[3];
        else if (lane == 22) nllv = __logf(rs) - s_tlogit[2];
        else if (lane == 28) nllv = __logf(rs) - s_tlogit[1];

        const unsigned FULL = 0xffffffffu;
        int   g3i = __shfl_sync(FULL, rai,  0);
        int   g2i = __shfl_sync(FULL, rai, 22);
        int   g1i = __shfl_sync(FULL, rai, 28);
        int   g0i = __shfl_sync(FULL, rai, 30);
        float nll3 = __shfl_sync(FULL, nllv,  0);
        float nll2 = __shfl_sync(FULL, nllv, 22);
        float nll1 = __shfl_sync(FULL, nllv, 28);

        if (lane == 0) {
            const int g0 = g0i;
            const int g1 = g1i + 100;
            const int g2 = g2i + 500;
            const int g3 = g3i + 2500;

            // Three independent gathers issue together (MLP).
            float h01 = __ldg(&H[(size_t)g0 * NTOTAL + g1]);
            float h12 = __ldg(&H[(size_t)g1 * NTOTAL + g2]);
            float h23 = __ldg(&H[(size_t)g2 * NTOTAL + g3]);
            float c01 = (h01 == 1.0f) ? 1.0f : 0.0f;
            float c12 = (h12 == 1.0f) ? 1.0f : 0.0f;
            float c23 = (h23 == 1.0f) ? 1.0f : 0.0f;

            const float E    = 2.7182817459106445f;   // float32(np.e)
            const float invB = 1.0f / (float)BATCH;
            float p = 0.25f * (E * c01 + nll1 * invB)
                    + 0.15f * (E * c12 + nll2 * invB)
                    + 0.10f * (E * c23 + nll3 * invB);
            p = fmaxf(p, 0.0f);   // mathematically guaranteed; guards fixed-point

            unsigned long long fx =
                (unsigned long long)__float2ll_rn(p * 4294967296.0f);   // * 2^32
            unsigned long long old = atomicAdd(&g_acc, fx + (1ULL << 48));
            if ((old >> 48) == BATCH - 1) {
                unsigned long long tot = (old & 0xFFFFFFFFFFFFULL) + fx;
                out[0] = (float)((double)tot * (1.0 / 4294967296.0));
                g_acc = 0ULL;   // reset for graph replay
            }
        }
    }
}

extern "C" void kernel_launch(void* const* d_in, const int* in_sizes, int n_in,
                              void* d_out, int out_size) {
    const float* y_pred = (const float*)d_in[0];
    const int*   y_true = (const int*)d_in[1];
    const float* H      = (const float*)d_in[2];
    float*       out    = (float*)d_out;

    fused_taxanet_kernel<<<BATCH, THREADS>>>(y_pred, y_true, H, out);
}